// round 6
// baseline (speedup 1.0000x reference)
#include <cuda_runtime.h>
#include <cuda_bf16.h>

// T=50, H=W=8, NH=16, B=8, TP=TF=8, HIDDEN=512, RPE_COEF=16
#define NROW   22275          // 99*15*15
#define NROWP  22288          // padded to mult of 16
#define NHEAD  16
#define HIDDEN 512
#define HPAD   20             // smem row stride (floats)

// Scratch: g_rpt[nh][row] = 16*sigmoid( (relu(rct@W1+b1)@W2)[row][nh] )
__device__ float g_rpt[NHEAD * NROWP];

// ---- packed f32x2 helpers (Blackwell) --------------------------------------
__device__ __forceinline__ unsigned long long pk64(float lo, float hi) {
    unsigned long long r;
    asm("mov.b64 %0, {%1, %2};" : "=l"(r) : "f"(lo), "f"(hi));
    return r;
}
__device__ __forceinline__ void upk64(unsigned long long v, float& lo, float& hi) {
    asm("mov.b64 {%0, %1}, %2;" : "=f"(lo), "=f"(hi) : "l"(v));
}
__device__ __forceinline__ unsigned long long fma2(unsigned long long a,
                                                   unsigned long long b,
                                                   unsigned long long c) {
    unsigned long long d;
    asm("fma.rn.f32x2 %0, %1, %2, %3;" : "=l"(d) : "l"(a), "l"(b), "l"(c));
    return d;
}

// ---------------------------------------------------------------------------
// Kernel 1: cpb MLP, fused 16*sigmoid, transposed store.
// 16 rows/block, 512 threads (16 warps) -> 4 blocks/SM = 2048 thr (max occ).
//  Phase 1: warp w computes hidden for row row0+w.
//  Phase 2: warp w owns h-slice [w*32, w*32+32); thread = (nh, 8 rows);
//           4 x fma.rn.f32x2 per h; 16-way bank-padded smem reduction.
// ---------------------------------------------------------------------------
__global__ void __launch_bounds__(512) mlp_kernel(
    const float* __restrict__ rct,   // [NROW, 3]
    const float* __restrict__ W1,    // [3, 512]
    const float* __restrict__ b1,    // [512]
    const float* __restrict__ W2)    // [512, 16]
{
    __shared__ float sH[HIDDEN * HPAD];     // 40 KB: sH[h*HPAD + r], r in [0,16)
    const int t    = threadIdx.x;
    const int w    = t >> 5;                // warp 0..15
    const int lane = t & 31;
    const int row0 = blockIdx.x * 16;

    // ---- Phase 1: hidden layer. Warp w -> row row0 + w. ----
    {
        const int r = row0 + w;
        float c0 = 0.f, c1 = 0.f, c2 = 0.f;
        if (r < NROW) {
            c0 = __ldg(rct + r * 3 + 0);
            c1 = __ldg(rct + r * 3 + 1);
            c2 = __ldg(rct + r * 3 + 2);
        }
        #pragma unroll 4
        for (int i = 0; i < 16; i++) {
            const int h  = i * 32 + lane;
            const float w0 = __ldg(W1 + h);
            const float w1 = __ldg(W1 + HIDDEN + h);
            const float w2 = __ldg(W1 + 2 * HIDDEN + h);
            const float bb = __ldg(b1 + h);
            sH[h * HPAD + w] =
                fmaxf(fmaf(c2, w2, fmaf(c1, w1, fmaf(c0, w0, bb))), 0.f);
        }
    }
    __syncthreads();

    // ---- Phase 2: layer 2, 32-h slice per warp ----
    const int oct = lane >> 4;              // rows oct*8 .. oct*8+7
    const int nh  = lane & 15;
    unsigned long long acc0 = 0ull, acc1 = 0ull, acc2 = 0ull, acc3 = 0ull;
    const int h0 = w * 32;
    const float* __restrict__ w2p = W2 + nh;
    #pragma unroll 4
    for (int i = 0; i < 32; i++) {
        const int h = h0 + i;
        const float wv = __ldg(w2p + h * NHEAD);         // L1-resident (32 KB)
        const unsigned long long ww = pk64(wv, wv);
        const float4 ha = *reinterpret_cast<const float4*>(&sH[h * HPAD + oct * 8]);
        const float4 hb = *reinterpret_cast<const float4*>(&sH[h * HPAD + oct * 8 + 4]);
        acc0 = fma2(pk64(ha.x, ha.y), ww, acc0);
        acc1 = fma2(pk64(ha.z, ha.w), ww, acc1);
        acc2 = fma2(pk64(hb.x, hb.y), ww, acc2);
        acc3 = fma2(pk64(hb.z, hb.w), ww, acc3);
    }
    __syncthreads();                         // done reading sH: reuse for reduction

    float a[8];
    upk64(acc0, a[0], a[1]); upk64(acc1, a[2], a[3]);
    upk64(acc2, a[4], a[5]); upk64(acc3, a[6], a[7]);

    // 16-way reduction: warps 1..15 store (stride-9 -> conflict-free),
    // warp 0 accumulates, activates, writes.
    float* sRed = sH;
    if (w > 0) {
        const int base = ((w - 1) * 32 + lane) * 9;
        #pragma unroll
        for (int j = 0; j < 8; j++) sRed[base + j] = a[j];
    }
    __syncthreads();
    if (w == 0) {
        #pragma unroll
        for (int q = 0; q < 15; q++) {
            const int base = (q * 32 + lane) * 9;
            #pragma unroll
            for (int j = 0; j < 8; j++) a[j] += sRed[base + j];
        }
        #pragma unroll
        for (int j = 0; j < 8; j++) a[j] = 16.f / (1.f + __expf(-a[j]));
        // rows beyond NROW (< NROWP) are harmless: gather never reads them.
        float* dst = g_rpt + nh * NROWP + row0 + oct * 8;
        *reinterpret_cast<float4*>(dst)     = make_float4(a[0], a[1], a[2], a[3]);
        *reinterpret_cast<float4*>(dst + 4) = make_float4(a[4], a[5], a[6], a[7]);
    }
}

// ---------------------------------------------------------------------------
// Kernel 2: gather. One block per (b, nh, tf, tp) 64x64 tile.
// vtab[wf][dh+7][par] holds the 240 distinct output float4s. All index math
// is loop-invariant:  hf = b0 + 2k (exact, no wrap), so vtab idx = base0+4k
// and the output pointer advances by a constant 2048 float4s.
// Hot loop: 1 LDS.128 + 1 STG.128, zero ALU.
// ---------------------------------------------------------------------------
__global__ void __launch_bounds__(256) gather_kernel(
    const int* __restrict__ ptc,     // [B, 8] (non-positive; time = -ptc)
    const int* __restrict__ ftc,     // [B, 8]
    float4* __restrict__ out)        // [B, 16, 512, 512] / 4
{
    __shared__ float4 vtab[240];     // [wf][dh+7][par] : wf*30 + dh7*2 + par
    const int tid = threadIdx.x;
    const int blk = blockIdx.x;
    const int tp = blk & 7;
    const int tf = (blk >> 3) & 7;
    const int nh = (blk >> 6) & 15;
    const int b  = blk >> 10;

    const int t_f =  __ldg(ftc + b * 8 + tf);
    const int t_p = -__ldg(ptc + b * 8 + tp);
    const float* __restrict__ src = g_rpt + nh * NROWP + (t_f + t_p) * 225;

    if (tid < 240) {
        const int wf  = tid / 30;
        const int rem = tid - wf * 30;
        const int dh7 = rem >> 1;
        const int par = rem & 1;                       // wp0 = par*4
        const int si  = dh7 * 15 + wf - par * 4 + 7;   // in [3, 224]
        vtab[tid] = make_float4(__ldg(src + si),     __ldg(src + si - 1),
                                __ldg(src + si - 2), __ldg(src + si - 3));
    }
    __syncthreads();

    // Loop-invariant decomposition of j = tid + k*256:
    //   c4 = tid & 15, fhw = (tid>>4) + 16k, wf = fhw&7 (inv), b0 = (tid>>4)>>3,
    //   hf = b0 + 2k (<= 7 always), hp = c4>>1, par = c4&1.
    const int c4    = tid & 15;
    const int fhw0  = tid >> 4;            // 0..15
    const int wf    = fhw0 & 7;
    const int b0    = fhw0 >> 3;           // 0 or 1
    const int hp    = c4 >> 1;
    const int par   = c4 & 1;
    const int base0 = wf * 30 + (b0 - hp + 7) * 2 + par;   // k=0 index

    float4* __restrict__ p =
        out + ((((b * NHEAD + nh) * 512 + tf * 64) * 512 + tp * 64) >> 2)
            + fhw0 * 128 + c4;

    #pragma unroll
    for (int k = 0; k < 4; k++) {
        __stcs(p, vtab[base0 + 4 * k]);    // idx = wf*30 + (b0+2k-hp+7)*2 + par
        p += 2048;                          // fhw += 16
    }
}

// ---------------------------------------------------------------------------
// Launch. Input order: ptc, ftc, W1, b1, W2, rct, rpi_table (unused).
// ---------------------------------------------------------------------------
extern "C" void kernel_launch(void* const* d_in, const int* in_sizes, int n_in,
                              void* d_out, int out_size)
{
    const int*   ptc = (const int*)  d_in[0];
    const int*   ftc = (const int*)  d_in[1];
    const float* W1  = (const float*)d_in[2];
    const float* b1  = (const float*)d_in[3];
    const float* W2  = (const float*)d_in[4];
    const float* rct = (const float*)d_in[5];

    mlp_kernel<<<NROWP / 16, 512>>>(rct, W1, b1, W2);

    // 8192 blocks: one per (b, nh, tf, tp) 64x64 tile
    gather_kernel<<<8 * NHEAD * 8 * 8, 256>>>(ptc, ftc, (float4*)d_out);
}

// round 7
// speedup vs baseline: 1.1901x; 1.1901x over previous
#include <cuda_runtime.h>
#include <cuda_bf16.h>

// T=50, H=W=8, NH=16, B=8, TP=TF=8, HIDDEN=512, RPE_COEF=16
#define NROW   22275          // 99*15*15
#define NROWP  22288          // padded to mult of 16
#define NHEAD  16
#define HIDDEN 512

// Scratch: g_rpt[nh][row] = 16*sigmoid( (relu(rct@W1+b1)@W2)[row][nh] )
__device__ float g_rpt[NHEAD * NROWP];

// ---- packed f32x2 helpers (Blackwell) --------------------------------------
__device__ __forceinline__ unsigned long long pk64(float lo, float hi) {
    unsigned long long r;
    asm("mov.b64 %0, {%1, %2};" : "=l"(r) : "f"(lo), "f"(hi));
    return r;
}
__device__ __forceinline__ void upk64(unsigned long long v, float& lo, float& hi) {
    asm("mov.b64 {%0, %1}, %2;" : "=f"(lo), "=f"(hi) : "l"(v));
}
__device__ __forceinline__ unsigned long long fma2(unsigned long long a,
                                                   unsigned long long b,
                                                   unsigned long long c) {
    unsigned long long d;
    asm("fma.rn.f32x2 %0, %1, %2, %3;" : "=l"(d) : "l"(a), "l"(b), "l"(c));
    return d;
}

// ---------------------------------------------------------------------------
// Kernel 1: FUSED cpb MLP. No smem hidden buffer (that was the bottleneck:
// 16x redundant LDS re-reads of hidden). Each thread owns (row, 128-h slice),
// computes hidden in registers and immediately accumulates 16 nh outputs via
// 8 x fma.rn.f32x2. W1/b1 and W2 are staged in smem and read as BROADCAST
// LDS.128 (conflict-free). 4 slices per row reduced through padded smem once.
// Block: 256 threads = 64 rows x 4 slices. Grid: 349 blocks.
// ---------------------------------------------------------------------------
__global__ void __launch_bounds__(256) mlp_kernel(
    const float* __restrict__ rct,   // [NROW, 3]
    const float* __restrict__ W1,    // [3, 512]
    const float* __restrict__ b1,    // [512]
    const float* __restrict__ W2)    // [512, 16]
{
    __shared__ float4 sW14[HIDDEN];              // 8 KB : {W1_0, W1_1, W1_2, b1}[h]
    __shared__ float4 sW2 [HIDDEN * 4];          // 32 KB: W2 rows as 4 float4 each
    const int tid = threadIdx.x;
    const int r   = tid & 63;                    // row within block
    const int s   = tid >> 6;                    // h-slice 0..3
    const int row0 = blockIdx.x * 64;
    const int row  = row0 + r;

    // Stage weights
    #pragma unroll
    for (int i = tid; i < HIDDEN; i += 256)
        sW14[i] = make_float4(__ldg(W1 + i), __ldg(W1 + HIDDEN + i),
                              __ldg(W1 + 2 * HIDDEN + i), __ldg(b1 + i));
    {
        const float4* __restrict__ w2v = reinterpret_cast<const float4*>(W2);
        #pragma unroll
        for (int i = tid; i < HIDDEN * 4; i += 256) sW2[i] = __ldg(w2v + i);
    }

    float c0 = 0.f, c1 = 0.f, c2 = 0.f;
    if (row < NROW) {
        c0 = __ldg(rct + row * 3 + 0);
        c1 = __ldg(rct + row * 3 + 1);
        c2 = __ldg(rct + row * 3 + 2);
    }
    __syncthreads();

    // Main loop: 128 h per thread. All lanes in a warp share the slice s,
    // so every LDS.128 below is a broadcast (no bank conflicts, no 16x traffic).
    unsigned long long acc[8] = {0ull,0ull,0ull,0ull,0ull,0ull,0ull,0ull};
    const int h0 = s * 128;
    #pragma unroll 4
    for (int i = 0; i < 128; i++) {
        const int h = h0 + i;
        const float4 wc = sW14[h];
        const float  hv = fmaxf(fmaf(c2, wc.z, fmaf(c1, wc.y, fmaf(c0, wc.x, wc.w))), 0.f);
        const unsigned long long hh = pk64(hv, hv);
        const float4 wa = sW2[h * 4 + 0];
        const float4 wb = sW2[h * 4 + 1];
        const float4 wcc = sW2[h * 4 + 2];
        const float4 wd = sW2[h * 4 + 3];
        acc[0] = fma2(hh, pk64(wa.x,  wa.y),  acc[0]);
        acc[1] = fma2(hh, pk64(wa.z,  wa.w),  acc[1]);
        acc[2] = fma2(hh, pk64(wb.x,  wb.y),  acc[2]);
        acc[3] = fma2(hh, pk64(wb.z,  wb.w),  acc[3]);
        acc[4] = fma2(hh, pk64(wcc.x, wcc.y), acc[4]);
        acc[5] = fma2(hh, pk64(wcc.z, wcc.w), acc[5]);
        acc[6] = fma2(hh, pk64(wd.x,  wd.y),  acc[6]);
        acc[7] = fma2(hh, pk64(wd.z,  wd.w),  acc[7]);
    }
    __syncthreads();     // done with sW2: reuse as reduction scratch

    // Partials: sRed[s][r][nh], row stride 17 floats (conflict-free STS.32)
    float* sRed = reinterpret_cast<float*>(sW2);      // needs 4*64*17*4B = 17.4 KB
    {
        float a[16];
        #pragma unroll
        for (int j = 0; j < 8; j++) upk64(acc[j], a[2 * j], a[2 * j + 1]);
        const int base = s * 1088 + r * 17;
        #pragma unroll
        for (int j = 0; j < 16; j++) sRed[base + j] = a[j];
    }
    __syncthreads();

    // Finalize: thread -> (nh = tid>>4, 4 rows). Sum 4 slices, sigmoid, float4 store.
    {
        const int nh  = tid >> 4;
        const int r16 = tid & 15;
        if (row0 + r16 * 4 < NROWP) {
            float v[4];
            #pragma unroll
            for (int q = 0; q < 4; q++) {
                const int rr = r16 * 4 + q;
                float sum = sRed[rr * 17 + nh]
                          + sRed[1088 + rr * 17 + nh]
                          + sRed[2176 + rr * 17 + nh]
                          + sRed[3264 + rr * 17 + nh];
                v[q] = 16.f / (1.f + __expf(-sum));
            }
            *reinterpret_cast<float4*>(g_rpt + nh * NROWP + row0 + r16 * 4) =
                make_float4(v[0], v[1], v[2], v[3]);
        }
    }
}

// ---------------------------------------------------------------------------
// Kernel 2: gather (at the HBM-write floor; unchanged from R6).
// One block per (b, nh, tf, tp) 64x64 tile; vtab holds the 240 distinct
// output float4s; hot loop = 1 LDS.128 + 1 streaming STG.128.
//   idx = (t_f + t_p)*225 + (hf-hp+7)*15 + (wf-wp+7)
// ---------------------------------------------------------------------------
__global__ void __launch_bounds__(256) gather_kernel(
    const int* __restrict__ ptc,     // [B, 8] (non-positive; time = -ptc)
    const int* __restrict__ ftc,     // [B, 8]
    float4* __restrict__ out)        // [B, 16, 512, 512] / 4
{
    __shared__ float4 vtab[240];     // [wf][dh+7][par] : wf*30 + dh7*2 + par
    const int tid = threadIdx.x;
    const int blk = blockIdx.x;
    const int tp = blk & 7;
    const int tf = (blk >> 3) & 7;
    const int nh = (blk >> 6) & 15;
    const int b  = blk >> 10;

    const int t_f =  __ldg(ftc + b * 8 + tf);
    const int t_p = -__ldg(ptc + b * 8 + tp);
    const float* __restrict__ src = g_rpt + nh * NROWP + (t_f + t_p) * 225;

    if (tid < 240) {
        const int wf  = tid / 30;
        const int rem = tid - wf * 30;
        const int dh7 = rem >> 1;
        const int par = rem & 1;                       // wp0 = par*4
        const int si  = dh7 * 15 + wf - par * 4 + 7;   // in [3, 224]
        vtab[tid] = make_float4(__ldg(src + si),     __ldg(src + si - 1),
                                __ldg(src + si - 2), __ldg(src + si - 3));
    }
    __syncthreads();

    const int c4    = tid & 15;
    const int fhw0  = tid >> 4;            // 0..15
    const int wf    = fhw0 & 7;
    const int b0    = fhw0 >> 3;           // 0 or 1
    const int hp    = c4 >> 1;
    const int par   = c4 & 1;
    const int base0 = wf * 30 + (b0 - hp + 7) * 2 + par;   // k=0 index

    float4* __restrict__ p =
        out + ((((b * NHEAD + nh) * 512 + tf * 64) * 512 + tp * 64) >> 2)
            + fhw0 * 128 + c4;

    #pragma unroll
    for (int k = 0; k < 4; k++) {
        __stcs(p, vtab[base0 + 4 * k]);    // hf = b0 + 2k, always <= 7
        p += 2048;                          // fhw += 16
    }
}

// ---------------------------------------------------------------------------
// Launch. Input order: ptc, ftc, W1, b1, W2, rct, rpi_table (unused).
// ---------------------------------------------------------------------------
extern "C" void kernel_launch(void* const* d_in, const int* in_sizes, int n_in,
                              void* d_out, int out_size)
{
    const int*   ptc = (const int*)  d_in[0];
    const int*   ftc = (const int*)  d_in[1];
    const float* W1  = (const float*)d_in[2];
    const float* b1  = (const float*)d_in[3];
    const float* W2  = (const float*)d_in[4];
    const float* rct = (const float*)d_in[5];

    // 349 blocks x 64 rows covers NROWP (stores bounds-guarded)
    mlp_kernel<<<(NROWP + 63) / 64, 256>>>(rct, W1, b1, W2);

    // 8192 blocks: one per (b, nh, tf, tp) 64x64 tile
    gather_kernel<<<8 * NHEAD * 8 * 8, 256>>>(ptc, ftc, (float4*)d_out);
}

// round 8
// speedup vs baseline: 1.3243x; 1.1128x over previous
#include <cuda_runtime.h>
#include <cuda_bf16.h>

// T=50, H=W=8, NH=16, B=8, TP=TF=8, HIDDEN=512, RPE_COEF=16
#define NROW   22275          // 99*15*15
#define NROWP  22336          // 349 * 64 (block coverage, no guards)
#define NHEAD  16
#define HIDDEN 512

// Scratch: g_rpt[nh][row] = 16*sigmoid( (relu(rct@W1+b1)@W2)[row][nh] )
__device__ float g_rpt[NHEAD * NROWP];

// ---- packed f32x2 helpers (Blackwell) --------------------------------------
__device__ __forceinline__ unsigned long long pk64(float lo, float hi) {
    unsigned long long r;
    asm("mov.b64 %0, {%1, %2};" : "=l"(r) : "f"(lo), "f"(hi));
    return r;
}
__device__ __forceinline__ void upk64(unsigned long long v, float& lo, float& hi) {
    asm("mov.b64 {%0, %1}, %2;" : "=f"(lo), "=f"(hi) : "l"(v));
}
__device__ __forceinline__ unsigned long long fma2(unsigned long long a,
                                                   unsigned long long b,
                                                   unsigned long long c) {
    unsigned long long d;
    asm("fma.rn.f32x2 %0, %1, %2, %3;" : "=l"(d) : "l"(a), "l"(b), "l"(c));
    return d;
}

// ---------------------------------------------------------------------------
// Kernel 1: FUSED cpb MLP, 2 rows per thread (halves W2 LDS traffic, which
// the R7 cycle model showed co-binding with the fma pipe).
//  Block: 256 threads = 8 warps. Warp w = h-slice [w*64, w*64+64).
//  Lane l = row pair (row0 + 2l, row0 + 2l + 1); 64 rows per block.
//  Per h: 1 LDS.128 (W1|b1) + 4 LDS.128 (W2, broadcast) + 8 hidden FMA +
//         16 fma.rn.f32x2 (16 nh x 2 rows).
//  8-slice reduction through bank-padded smem (reuses the weight smem).
// ---------------------------------------------------------------------------
__global__ void __launch_bounds__(256) mlp_kernel(
    const float* __restrict__ rct,   // [NROW, 3]
    const float* __restrict__ W1,    // [3, 512]
    const float* __restrict__ b1,    // [512]
    const float* __restrict__ W2)    // [512, 16]
{
    __shared__ float smem[10240];                     // 40 KB
    float4* sW14 = reinterpret_cast<float4*>(smem);         // [512]  {W1_0,W1_1,W1_2,b1}
    float4* sW2  = reinterpret_cast<float4*>(smem + 2048);  // [2048] W2 rows (4 float4 each)

    const int tid  = threadIdx.x;
    const int wid  = tid >> 5;
    const int lane = tid & 31;
    const int row0 = blockIdx.x * 64;

    // Stage weights (all L2-hit after first blocks)
    #pragma unroll
    for (int i = tid; i < HIDDEN; i += 256)
        sW14[i] = make_float4(__ldg(W1 + i), __ldg(W1 + HIDDEN + i),
                              __ldg(W1 + 2 * HIDDEN + i), __ldg(b1 + i));
    {
        const float4* __restrict__ w2v = reinterpret_cast<const float4*>(W2);
        #pragma unroll
        for (int i = tid; i < HIDDEN * 4; i += 256) sW2[i] = __ldg(w2v + i);
    }

    const int r0 = row0 + 2 * lane;
    const int r1 = r0 + 1;
    float c0a = 0.f, c1a = 0.f, c2a = 0.f, c0b = 0.f, c1b = 0.f, c2b = 0.f;
    if (r0 < NROW) { c0a = __ldg(rct + r0 * 3 + 0);
                     c1a = __ldg(rct + r0 * 3 + 1);
                     c2a = __ldg(rct + r0 * 3 + 2); }
    if (r1 < NROW) { c0b = __ldg(rct + r1 * 3 + 0);
                     c1b = __ldg(rct + r1 * 3 + 1);
                     c2b = __ldg(rct + r1 * 3 + 2); }
    __syncthreads();

    // Main loop: 64 h per warp-slice; every LDS is a single-address broadcast.
    unsigned long long acc[16];
    #pragma unroll
    for (int j = 0; j < 16; j++) acc[j] = 0ull;
    const int h0 = wid * 64;
    #pragma unroll 4
    for (int i = 0; i < 64; i++) {
        const int h = h0 + i;
        const float4 wc = sW14[h];
        const float hv0 = fmaxf(fmaf(c2a, wc.z, fmaf(c1a, wc.y, fmaf(c0a, wc.x, wc.w))), 0.f);
        const float hv1 = fmaxf(fmaf(c2b, wc.z, fmaf(c1b, wc.y, fmaf(c0b, wc.x, wc.w))), 0.f);
        const unsigned long long hh0 = pk64(hv0, hv0);
        const unsigned long long hh1 = pk64(hv1, hv1);
        const float4 wa = sW2[h * 4 + 0];
        const float4 wb = sW2[h * 4 + 1];
        const float4 wc2 = sW2[h * 4 + 2];
        const float4 wd = sW2[h * 4 + 3];
        const unsigned long long p0 = pk64(wa.x,  wa.y),  p1 = pk64(wa.z,  wa.w);
        const unsigned long long p2 = pk64(wb.x,  wb.y),  p3 = pk64(wb.z,  wb.w);
        const unsigned long long p4 = pk64(wc2.x, wc2.y), p5 = pk64(wc2.z, wc2.w);
        const unsigned long long p6 = pk64(wd.x,  wd.y),  p7 = pk64(wd.z,  wd.w);
        acc[0]  = fma2(hh0, p0, acc[0]);   acc[1]  = fma2(hh0, p1, acc[1]);
        acc[2]  = fma2(hh0, p2, acc[2]);   acc[3]  = fma2(hh0, p3, acc[3]);
        acc[4]  = fma2(hh0, p4, acc[4]);   acc[5]  = fma2(hh0, p5, acc[5]);
        acc[6]  = fma2(hh0, p6, acc[6]);   acc[7]  = fma2(hh0, p7, acc[7]);
        acc[8]  = fma2(hh1, p0, acc[8]);   acc[9]  = fma2(hh1, p1, acc[9]);
        acc[10] = fma2(hh1, p2, acc[10]);  acc[11] = fma2(hh1, p3, acc[11]);
        acc[12] = fma2(hh1, p4, acc[12]);  acc[13] = fma2(hh1, p5, acc[13]);
        acc[14] = fma2(hh1, p6, acc[14]);  acc[15] = fma2(hh1, p7, acc[15]);
    }
    __syncthreads();     // weights no longer needed: reuse smem for reduction

    // Partials: sRed[s][r][nh], row stride 17 floats. 8*64*17 = 8704 floats.
    {
        float a[32];
        #pragma unroll
        for (int j = 0; j < 16; j++) upk64(acc[j], a[2 * j], a[2 * j + 1]);
        const int base0 = wid * 1088 + (2 * lane) * 17;
        #pragma unroll
        for (int j = 0; j < 16; j++) smem[base0 + j]      = a[j];        // row r0
        #pragma unroll
        for (int j = 0; j < 16; j++) smem[base0 + 17 + j] = a[16 + j];   // row r1
    }
    __syncthreads();

    // Finalize: thread = (nh = tid&15, 4 rows). Sum 8 slices, sigmoid, float4 store.
    {
        const int nh = tid & 15;
        const int rq = tid >> 4;             // 0..15 -> rows rq*4 .. rq*4+3
        float v[4];
        #pragma unroll
        for (int q = 0; q < 4; q++) {
            const int r = rq * 4 + q;
            float sum = 0.f;
            #pragma unroll
            for (int s = 0; s < 8; s++) sum += smem[s * 1088 + r * 17 + nh];
            v[q] = 16.f / (1.f + __expf(-sum));
        }
        *reinterpret_cast<float4*>(g_rpt + nh * NROWP + row0 + rq * 4) =
            make_float4(v[0], v[1], v[2], v[3]);
    }
}

// ---------------------------------------------------------------------------
// Kernel 2: gather (at the HBM-write floor; unchanged).
// One block per (b, nh, tf, tp) 64x64 tile; vtab holds the 240 distinct
// output float4s; hot loop = 1 LDS.128 + 1 streaming STG.128.
//   idx = (t_f + t_p)*225 + (hf-hp+7)*15 + (wf-wp+7)
// ---------------------------------------------------------------------------
__global__ void __launch_bounds__(256) gather_kernel(
    const int* __restrict__ ptc,     // [B, 8] (non-positive; time = -ptc)
    const int* __restrict__ ftc,     // [B, 8]
    float4* __restrict__ out)        // [B, 16, 512, 512] / 4
{
    __shared__ float4 vtab[240];     // [wf][dh+7][par] : wf*30 + dh7*2 + par
    const int tid = threadIdx.x;
    const int blk = blockIdx.x;
    const int tp = blk & 7;
    const int tf = (blk >> 3) & 7;
    const int nh = (blk >> 6) & 15;
    const int b  = blk >> 10;

    const int t_f =  __ldg(ftc + b * 8 + tf);
    const int t_p = -__ldg(ptc + b * 8 + tp);
    const float* __restrict__ src = g_rpt + nh * NROWP + (t_f + t_p) * 225;

    if (tid < 240) {
        const int wf  = tid / 30;
        const int rem = tid - wf * 30;
        const int dh7 = rem >> 1;
        const int par = rem & 1;                       // wp0 = par*4
        const int si  = dh7 * 15 + wf - par * 4 + 7;   // in [3, 224]
        vtab[tid] = make_float4(__ldg(src + si),     __ldg(src + si - 1),
                                __ldg(src + si - 2), __ldg(src + si - 3));
    }
    __syncthreads();

    const int c4    = tid & 15;
    const int fhw0  = tid >> 4;            // 0..15
    const int wf    = fhw0 & 7;
    const int b0    = fhw0 >> 3;           // 0 or 1
    const int hp    = c4 >> 1;
    const int par   = c4 & 1;
    const int base0 = wf * 30 + (b0 - hp + 7) * 2 + par;   // k=0 index

    float4* __restrict__ p =
        out + ((((b * NHEAD + nh) * 512 + tf * 64) * 512 + tp * 64) >> 2)
            + fhw0 * 128 + c4;

    #pragma unroll
    for (int k = 0; k < 4; k++) {
        __stcs(p, vtab[base0 + 4 * k]);    // hf = b0 + 2k, always <= 7
        p += 2048;                          // fhw += 16
    }
}

// ---------------------------------------------------------------------------
// Launch. Input order: ptc, ftc, W1, b1, W2, rct, rpi_table (unused).
// ---------------------------------------------------------------------------
extern "C" void kernel_launch(void* const* d_in, const int* in_sizes, int n_in,
                              void* d_out, int out_size)
{
    const int*   ptc = (const int*)  d_in[0];
    const int*   ftc = (const int*)  d_in[1];
    const float* W1  = (const float*)d_in[2];
    const float* b1  = (const float*)d_in[3];
    const float* W2  = (const float*)d_in[4];
    const float* rct = (const float*)d_in[5];

    // 349 blocks x 64 rows = 22336 rows (NROWP); rows >= NROW are never read.
    mlp_kernel<<<NROWP / 64, 256>>>(rct, W1, b1, W2);

    // 8192 blocks: one per (b, nh, tf, tp) 64x64 tile
    gather_kernel<<<8 * NHEAD * 8 * 8, 256>>>(ptc, ftc, (float4*)d_out);
}